// round 7
// baseline (speedup 1.0000x reference)
#include <cuda_runtime.h>
#include <cstdint>

#define FULLMASK 0xffffffffu

constexpr int B_   = 64;
constexpr int N_   = 1024;
constexpr int D_   = 64;
constexpr int NNODES = B_ * N_;                 // 65536
constexpr int EDGES  = 1 << 20;                 // 1,048,576
constexpr int ROW_WORDS = N_ / 32;              // 32
constexpr int ADJ_WORDS = NNODES * ROW_WORDS;   // 2,097,152 (8 MB)

constexpr int ROWS_PER_BLOCK = 64;
constexpr int THREADS = 256;                     // 8 warps, 8 rows/warp
constexpr int LISTCAP  = 320;
constexpr int S_STRIDE = 66;
constexpr int W_STRIDE = 68;

// k_aggregate smem layout (floats):
constexpr int SM_S_OFF    = 0;                                // S[64][66]
constexpr int SM_W_OFF    = ROWS_PER_BLOCK * S_STRIDE;        // 4224
constexpr int SM_LIST_OFF = SM_W_OFF + 64 * W_STRIDE;         // 8576
constexpr int SM_BYTES    = SM_LIST_OFF * 4 + 8 * LISTCAP * 2; // 34304+5120=39424

// Scratch
__device__ unsigned g_adj[ADJ_WORDS];
__device__ unsigned g_pooled[B_ * D_];
__device__ int g_is64;

// Order-preserving float <-> uint map for atomicMax on floats
__device__ __forceinline__ unsigned fmap(float f) {
    unsigned u = __float_as_uint(f);
    return (u & 0x80000000u) ? ~u : (u | 0x80000000u);
}
__device__ __forceinline__ float funmap(unsigned u) {
    return (u & 0x80000000u) ? __uint_as_float(u ^ 0x80000000u)
                             : __uint_as_float(~u);
}

// ---- packed f32x2 helpers (Blackwell) ----
__device__ __forceinline__ unsigned long long pack2(float lo, float hi) {
    unsigned long long r;
    unsigned a = __float_as_uint(lo), b = __float_as_uint(hi);
    asm("mov.b64 %0, {%1, %2};" : "=l"(r) : "r"(a), "r"(b));
    return r;
}
__device__ __forceinline__ unsigned long long fma2(unsigned long long a,
                                                   unsigned long long b,
                                                   unsigned long long c) {
    unsigned long long d;
    asm("fma.rn.f32x2 %0, %1, %2, %3;" : "=l"(d) : "l"(a), "l"(b), "l"(c));
    return d;
}
__device__ __forceinline__ unsigned long long add2(unsigned long long a,
                                                   unsigned long long b) {
    unsigned long long d;
    asm("add.rn.f32x2 %0, %1, %2;" : "=l"(d) : "l"(a), "l"(b));
    return d;
}
__device__ __forceinline__ float lo2(unsigned long long u) { return __uint_as_float((unsigned)u); }
__device__ __forceinline__ float hi2(unsigned long long u) { return __uint_as_float((unsigned)(u >> 32)); }

union F4U {
    float4 f;
    unsigned long long u[2];
};

// W bank swizzle: 4-float chunks; upper-half chunks rotated by 4 words
__device__ __host__ __forceinline__ int wphys(int dc) {
    return (dc < 32) ? dc : ((((dc + 4) & 31)) | 32);
}

// ---------------------------------------------------------------------------
// 1) Clear bitmap + pooled accumulator; fold in int64/int32 detection
// ---------------------------------------------------------------------------
__global__ void k_clear(const void* ei) {
    unsigned idx = blockIdx.x * blockDim.x + threadIdx.x;
    if (idx == 0) {
        const long long* p = (const long long*)ei;
        int is64 = 1;
        for (int i = 0; i < 16; i++) {
            long long v = p[i];
            if (v < 0 || v > 65535) is64 = 0;
        }
        g_is64 = is64;
    }
    const uint4 z = make_uint4(0, 0, 0, 0);
    constexpr unsigned ADJ_V4 = ADJ_WORDS / 4;
    constexpr unsigned POOL_V4 = (B_ * D_) / 4;
    if (idx < ADJ_V4) {
        ((uint4*)g_adj)[idx] = z;
    } else if (idx < ADJ_V4 + POOL_V4) {
        ((uint4*)g_pooled)[idx - ADJ_V4] = z;
    }
}

// ---------------------------------------------------------------------------
// 2) Edge scatter into bitmap (idempotent -> exact dedup). 2 edges/thread,
//    16B vector loads on both the start and end streams.
// ---------------------------------------------------------------------------
__global__ void k_scatter(const void* ei_raw) {
    int e2 = blockIdx.x * blockDim.x + threadIdx.x;   // pair index
    if (e2 >= EDGES / 2) return;
    int s0, t0, s1, t1;
    if (g_is64) {
        const longlong2* ps = (const longlong2*)ei_raw;
        longlong2 sv = ps[e2];
        longlong2 tv = ps[EDGES / 2 + e2];
        s0 = (int)sv.x; s1 = (int)sv.y;
        t0 = (int)tv.x; t1 = (int)tv.y;
    } else {
        const int2* ps = (const int2*)ei_raw;
        int2 sv = ps[e2];
        int2 tv = ps[EDGES / 2 + e2];
        s0 = sv.x; s1 = sv.y;
        t0 = tv.x; t1 = tv.y;
    }
    int l0 = t0 & (N_ - 1);
    int l1 = t1 & (N_ - 1);
    atomicOr(&g_adj[s0 * ROW_WORDS + (l0 >> 5)], 1u << (l0 & 31));
    atomicOr(&g_adj[s1 * ROW_WORDS + (l1 >> 5)], 1u << (l1 & 31));
}

// ---------------------------------------------------------------------------
// 3) Fused gather + transform + max-pool. 64 rows/block.
// ---------------------------------------------------------------------------
__global__ __launch_bounds__(THREADS)
void k_aggregate(const float* __restrict__ x,
                 const float* __restrict__ W,
                 const float* __restrict__ bias) {
    extern __shared__ float smem[];
    float* S   = smem + SM_S_OFF;
    float* Wsh = smem + SM_W_OFF;
    unsigned short* listAll = (unsigned short*)(smem + SM_LIST_OFF);

    const int tid  = threadIdx.x;
    const int warp = tid >> 5;
    const int lane = tid & 31;
    const int g    = blockIdx.x >> 4;            // 64 rows/block, 16 blocks/graph

    // ---- stage W (swizzled) ----
    for (int idx = tid; idx < 64 * 64; idx += THREADS) {
        int k = idx >> 6, d = idx & 63;
        Wsh[k * W_STRIDE + wphys(d & ~3) + (d & 3)] = W[idx];
    }

    // ---- Phase A: gather ----
    {
        const int h   = lane >> 4;
        const int l16 = lane & 15;
        const int off = l16 << 2;
        unsigned short* lst = listAll + warp * LISTCAP;
        const float* xg = x + ((size_t)g << 16);

        const int rowBase = blockIdx.x * ROWS_PER_BLOCK + warp * 8;
        unsigned wordNext = g_adj[rowBase * ROW_WORDS + lane];

        for (int i = 0; i < 8; i++) {
            const int lr = warp * 8 + i;
            unsigned word = wordNext;
            if (i < 7)
                wordNext = g_adj[(rowBase + i + 1) * ROW_WORDS + lane];

            // decode bitmap row -> compact neighbor list
            int cnt = __popc(word);
            int pre = cnt;
#pragma unroll
            for (int o = 1; o < 32; o <<= 1) {
                int v = __shfl_up_sync(FULLMASK, pre, o);
                if (lane >= o) pre += v;
            }
            int deg = __shfl_sync(FULLMASK, pre, 31);
            pre -= cnt;
            while (word) {
                int b = __ffs(word) - 1;
                word &= word - 1;
                if (pre < LISTCAP) lst[pre] = (unsigned short)((lane << 5) | b);
                pre++;
            }
            if (deg > LISTCAP) deg = LISTCAP;
            __syncwarp();

            // half-warp pair gather, unrolled x4, two f32x2 accumulator chains
            unsigned long long a0 = 0ull, a1 = 0ull, b0 = 0ull, b1 = 0ull;
            const int nfull = deg >> 1;
            int t = 0;
            for (; t + 4 <= nfull; t += 4) {
                int i0 = (int)lst[2 * t + h];
                int i1 = (int)lst[2 * (t + 1) + h];
                int i2 = (int)lst[2 * (t + 2) + h];
                int i3 = (int)lst[2 * (t + 3) + h];
                F4U v0, v1, v2, v3;
                v0.f = __ldg((const float4*)(xg + (i0 << 6) + off));
                v1.f = __ldg((const float4*)(xg + (i1 << 6) + off));
                v2.f = __ldg((const float4*)(xg + (i2 << 6) + off));
                v3.f = __ldg((const float4*)(xg + (i3 << 6) + off));
                a0 = add2(a0, v0.u[0]); a1 = add2(a1, v0.u[1]);
                b0 = add2(b0, v1.u[0]); b1 = add2(b1, v1.u[1]);
                a0 = add2(a0, v2.u[0]); a1 = add2(a1, v2.u[1]);
                b0 = add2(b0, v3.u[0]); b1 = add2(b1, v3.u[1]);
            }
            for (; t < nfull; t++) {
                int ni = (int)lst[2 * t + h];
                F4U v;
                v.f = __ldg((const float4*)(xg + (ni << 6) + off));
                a0 = add2(a0, v.u[0]);
                a1 = add2(a1, v.u[1]);
            }
            if ((deg & 1) && h == 0) {
                int ni = (int)lst[deg - 1];
                F4U v;
                v.f = __ldg((const float4*)(xg + (ni << 6) + off));
                b0 = add2(b0, v.u[0]);
                b1 = add2(b1, v.u[1]);
            }
            a0 = add2(a0, b0);
            a1 = add2(a1, b1);

            float s0 = lo2(a0), s1 = hi2(a0), s2 = lo2(a1), s3 = hi2(a1);
            s0 += __shfl_xor_sync(FULLMASK, s0, 16);
            s1 += __shfl_xor_sync(FULLMASK, s1, 16);
            s2 += __shfl_xor_sync(FULLMASK, s2, 16);
            s3 += __shfl_xor_sync(FULLMASK, s3, 16);
            if (h == 0) {
                float* Srow = &S[lr * S_STRIDE + 4 * l16];
                Srow[0] = s0; Srow[1] = s1; Srow[2] = s2; Srow[3] = s3;
            }
            __syncwarp();
        }
    }
    __syncthreads();

    // ---- Phase B: Y = S@W + bias, 2 rows x 8 dims / thread, f32x2 ----
    const int d0    = (lane & 7) * 8;
    const int rsub  = lane >> 3;
    const int rbase = warp * 8 + rsub * 2;
    const int pc0   = wphys(d0);
    const int pc1   = wphys(d0 + 4);

    unsigned long long acc[2][4];
    {
        unsigned long long bp[4];
#pragma unroll
        for (int p = 0; p < 4; p++)
            bp[p] = pack2(__ldg(&bias[d0 + 2 * p]), __ldg(&bias[d0 + 2 * p + 1]));
#pragma unroll
        for (int i = 0; i < 2; i++)
#pragma unroll
            for (int p = 0; p < 4; p++) acc[i][p] = bp[p];
    }

#pragma unroll 8
    for (int k = 0; k < 64; k++) {
        F4U wa, wb;
        wa.f = *reinterpret_cast<const float4*>(&Wsh[k * W_STRIDE + pc0]);
        wb.f = *reinterpret_cast<const float4*>(&Wsh[k * W_STRIDE + pc1]);
#pragma unroll
        for (int i = 0; i < 2; i++) {
            float s = S[(rbase + i) * S_STRIDE + k];
            unsigned long long sp = pack2(s, s);
            acc[i][0] = fma2(sp, wa.u[0], acc[i][0]);
            acc[i][1] = fma2(sp, wa.u[1], acc[i][1]);
            acc[i][2] = fma2(sp, wb.u[0], acc[i][2]);
            acc[i][3] = fma2(sp, wb.u[1], acc[i][3]);
        }
    }

    // ---- max-pool epilogue ----
    float m[8];
#pragma unroll
    for (int p = 0; p < 4; p++) {
        float m0 = fmaxf(lo2(acc[0][p]), lo2(acc[1][p]));
        float m1 = fmaxf(hi2(acc[0][p]), hi2(acc[1][p]));
        m[2 * p] = m0;
        m[2 * p + 1] = m1;
    }
#pragma unroll
    for (int j = 0; j < 8; j++) {
        m[j] = fmaxf(m[j], __shfl_xor_sync(FULLMASK, m[j], 8));
        m[j] = fmaxf(m[j], __shfl_xor_sync(FULLMASK, m[j], 16));
    }
    if (rsub == 0) {
#pragma unroll
        for (int j = 0; j < 8; j++)
            atomicMax(&g_pooled[g * 64 + d0 + j], fmap(m[j]));
    }
}

// ---------------------------------------------------------------------------
// 4) MLP head: ONE block, 256 threads. Weights + activations staged in smem,
//    register-blocked f32x2 GEMM per layer (64x64x64), tanh in registers.
// ---------------------------------------------------------------------------
constexpr int H_STRIDE = 66;
// mlp smem: H[64][66] + Wsh1[64][68] + Wsh2[64][68]
constexpr int MM_H_OFF  = 0;
constexpr int MM_W1_OFF = 64 * H_STRIDE;                 // 4224
constexpr int MM_W2_OFF = MM_W1_OFF + 64 * W_STRIDE;     // 8576
constexpr int MM_BYTES  = (MM_W2_OFF + 64 * W_STRIDE) * 4;  // ~51.7KB

__global__ __launch_bounds__(256)
void k_mlp(const float* __restrict__ w1, const float* __restrict__ b1,
           const float* __restrict__ w2, const float* __restrict__ b2,
           const float* __restrict__ w3, const float* __restrict__ b3,
           float* __restrict__ out) {
    extern __shared__ float sm[];
    float* H    = sm + MM_H_OFF;
    float* Wsh1 = sm + MM_W1_OFF;
    float* Wsh2 = sm + MM_W2_OFF;

    const int tid  = threadIdx.x;
    const int warp = tid >> 5;
    const int lane = tid & 31;

    // stage pooled H (funmap) and both weight matrices
    for (int idx = tid; idx < 64 * 64; idx += 256) {
        int r = idx >> 6, d = idx & 63;
        H[r * H_STRIDE + d] = funmap(g_pooled[idx]);
        int pw = (r) * W_STRIDE + wphys(d & ~3) + (d & 3);
        Wsh1[pw] = __ldg(&w1[idx]);
        Wsh2[pw] = __ldg(&w2[idx]);
    }
    __syncthreads();

    const int d0    = (lane & 7) * 8;
    const int rsub  = lane >> 3;
    const int rbase = warp * 8 + rsub * 2;     // 2 rows (graphs) per thread
    const int pc0   = wphys(d0);
    const int pc1   = wphys(d0 + 4);

    // ---- two tanh(GEMM) layers ----
    for (int layer = 0; layer < 2; layer++) {
        const float* Wl = (layer == 0) ? Wsh1 : Wsh2;
        const float* bl = (layer == 0) ? b1 : b2;

        unsigned long long acc[2][4];
        {
            unsigned long long bp[4];
#pragma unroll
            for (int p = 0; p < 4; p++)
                bp[p] = pack2(__ldg(&bl[d0 + 2 * p]), __ldg(&bl[d0 + 2 * p + 1]));
#pragma unroll
            for (int i = 0; i < 2; i++)
#pragma unroll
                for (int p = 0; p < 4; p++) acc[i][p] = bp[p];
        }
#pragma unroll 8
        for (int k = 0; k < 64; k++) {
            F4U wa, wb;
            wa.f = *reinterpret_cast<const float4*>(&Wl[k * W_STRIDE + pc0]);
            wb.f = *reinterpret_cast<const float4*>(&Wl[k * W_STRIDE + pc1]);
#pragma unroll
            for (int i = 0; i < 2; i++) {
                float s = H[(rbase + i) * H_STRIDE + k];
                unsigned long long sp = pack2(s, s);
                acc[i][0] = fma2(sp, wa.u[0], acc[i][0]);
                acc[i][1] = fma2(sp, wa.u[1], acc[i][1]);
                acc[i][2] = fma2(sp, wb.u[0], acc[i][2]);
                acc[i][3] = fma2(sp, wb.u[1], acc[i][3]);
            }
        }
        __syncthreads();   // all H reads done before overwrite
#pragma unroll
        for (int i = 0; i < 2; i++) {
            float* Hr = &H[(rbase + i) * H_STRIDE + d0];
#pragma unroll
            for (int p = 0; p < 4; p++) {
                Hr[2 * p]     = tanhf(lo2(acc[i][p]));
                Hr[2 * p + 1] = tanhf(hi2(acc[i][p]));
            }
        }
        __syncthreads();
    }

    // ---- layer 3: out[g] = dot(H[g], w3) + b3 ----
    if (tid < 64) {
        float p = 0.f;
        const float* Hr = &H[tid * H_STRIDE];
#pragma unroll 16
        for (int k = 0; k < 64; k++)
            p = fmaf(Hr[k], __ldg(&w3[k]), p);
        out[tid] = p + __ldg(&b3[0]);
    }
}

// ---------------------------------------------------------------------------
extern "C" void kernel_launch(void* const* d_in, const int* in_sizes, int n_in,
                              void* d_out, int out_size) {
    const float* x      = (const float*)d_in[0];
    const void*  eidx   = d_in[1];
    const float* weight = (const float*)d_in[4];
    const float* bias   = (const float*)d_in[5];
    const float* w1     = (const float*)d_in[6];
    const float* b1     = (const float*)d_in[7];
    const float* w2     = (const float*)d_in[8];
    const float* b2     = (const float*)d_in[9];
    const float* w3     = (const float*)d_in[10];
    const float* b3     = (const float*)d_in[11];
    float* out = (float*)d_out;

    cudaFuncSetAttribute(k_aggregate, cudaFuncAttributeMaxDynamicSharedMemorySize, SM_BYTES);
    cudaFuncSetAttribute(k_mlp, cudaFuncAttributeMaxDynamicSharedMemorySize, MM_BYTES);

    constexpr unsigned CLEAR_V4 = ADJ_WORDS / 4 + (B_ * D_) / 4;
    k_clear<<<(CLEAR_V4 + 255) / 256, 256>>>(eidx);

    k_scatter<<<(EDGES / 2) / 256, 256>>>(eidx);

    k_aggregate<<<NNODES / ROWS_PER_BLOCK, THREADS, SM_BYTES>>>(x, weight, bias);

    k_mlp<<<1, 256, MM_BYTES>>>(w1, b1, w2, b2, w3, b3, out);
}

// round 8
// speedup vs baseline: 1.4976x; 1.4976x over previous
#include <cuda_runtime.h>
#include <cstdint>

#define FULLMASK 0xffffffffu

constexpr int B_   = 64;
constexpr int N_   = 1024;
constexpr int D_   = 64;
constexpr int NNODES = B_ * N_;                 // 65536
constexpr int EDGES  = 1 << 20;                 // 1,048,576
constexpr int ROW_WORDS = N_ / 32;              // 32
constexpr int ADJ_WORDS = NNODES * ROW_WORDS;   // 2,097,152 (8 MB)

constexpr int ROWS_PER_BLOCK = 128;
constexpr int THREADS = 256;                     // 8 warps, 16 rows/warp
constexpr int LISTCAP  = 320;
constexpr int S_STRIDE = 66;
constexpr int W_STRIDE = 68;

// k_aggregate smem layout (floats):
constexpr int SM_S_OFF    = 0;                                // S[128][66]
constexpr int SM_W_OFF    = ROWS_PER_BLOCK * S_STRIDE;        // 8448
constexpr int SM_LIST_OFF = SM_W_OFF + 64 * W_STRIDE;         // 12800
constexpr int SM_BYTES    = SM_LIST_OFF * 4 + 8 * LISTCAP * 2; // 56320

// Scratch (zero-initialized at module load; every call restores the zeros)
__device__ unsigned g_adj[ADJ_WORDS];
__device__ unsigned g_pooled[B_ * D_];
__device__ int g_is64;

// Order-preserving float <-> uint map for atomicMax on floats
__device__ __forceinline__ unsigned fmap(float f) {
    unsigned u = __float_as_uint(f);
    return (u & 0x80000000u) ? ~u : (u | 0x80000000u);
}
__device__ __forceinline__ float funmap(unsigned u) {
    return (u & 0x80000000u) ? __uint_as_float(u ^ 0x80000000u)
                             : __uint_as_float(~u);
}

// ---- packed f32x2 helpers (Blackwell) ----
__device__ __forceinline__ unsigned long long pack2(float lo, float hi) {
    unsigned long long r;
    unsigned a = __float_as_uint(lo), b = __float_as_uint(hi);
    asm("mov.b64 %0, {%1, %2};" : "=l"(r) : "r"(a), "r"(b));
    return r;
}
__device__ __forceinline__ unsigned long long fma2(unsigned long long a,
                                                   unsigned long long b,
                                                   unsigned long long c) {
    unsigned long long d;
    asm("fma.rn.f32x2 %0, %1, %2, %3;" : "=l"(d) : "l"(a), "l"(b), "l"(c));
    return d;
}
__device__ __forceinline__ unsigned long long add2(unsigned long long a,
                                                   unsigned long long b) {
    unsigned long long d;
    asm("add.rn.f32x2 %0, %1, %2;" : "=l"(d) : "l"(a), "l"(b));
    return d;
}
__device__ __forceinline__ float lo2(unsigned long long u) { return __uint_as_float((unsigned)u); }
__device__ __forceinline__ float hi2(unsigned long long u) { return __uint_as_float((unsigned)(u >> 32)); }

union F4U {
    float4 f;
    unsigned long long u[2];
};

// W bank swizzle: 4-float chunks; upper-half chunks rotated by 4 words
__device__ __host__ __forceinline__ int wphys(int dc) {
    return (dc < 32) ? dc : ((((dc + 4) & 31)) | 32);
}

// ---------------------------------------------------------------------------
// 0) Detect int64 vs int32 edge_index
// ---------------------------------------------------------------------------
__global__ void k_detect(const void* ei) {
    if (threadIdx.x == 0) {
        const long long* p = (const long long*)ei;
        int is64 = 1;
        for (int i = 0; i < 16; i++) {
            long long v = p[i];
            if (v < 0 || v > 65535) is64 = 0;
        }
        g_is64 = is64;
    }
}

// ---------------------------------------------------------------------------
// 1) Edge scatter into bitmap (idempotent -> exact dedup). 2 edges/thread.
//    First 1024 threads also zero g_pooled (4096 words).
// ---------------------------------------------------------------------------
__global__ void k_scatter(const void* ei_raw) {
    int e2 = blockIdx.x * blockDim.x + threadIdx.x;   // pair index
    if (e2 < (B_ * D_) / 4) {
        ((uint4*)g_pooled)[e2] = make_uint4(0, 0, 0, 0);
    }
    if (e2 >= EDGES / 2) return;
    int s0, t0, s1, t1;
    if (g_is64) {
        const longlong2* ps = (const longlong2*)ei_raw;
        longlong2 sv = ps[e2];
        longlong2 tv = ps[EDGES / 2 + e2];
        s0 = (int)sv.x; s1 = (int)sv.y;
        t0 = (int)tv.x; t1 = (int)tv.y;
    } else {
        const int2* ps = (const int2*)ei_raw;
        int2 sv = ps[e2];
        int2 tv = ps[EDGES / 2 + e2];
        s0 = sv.x; s1 = sv.y;
        t0 = tv.x; t1 = tv.y;
    }
    int l0 = t0 & (N_ - 1);
    int l1 = t1 & (N_ - 1);
    atomicOr(&g_adj[s0 * ROW_WORDS + (l0 >> 5)], 1u << (l0 & 31));
    atomicOr(&g_adj[s1 * ROW_WORDS + (l1 >> 5)], 1u << (l1 & 31));
}

// ---------------------------------------------------------------------------
// 2) Fused gather + transform + max-pool. 128 rows/block (R5 config).
//    Each warp zeroes its bitmap row after decoding (restores invariant).
// ---------------------------------------------------------------------------
__global__ __launch_bounds__(THREADS)
void k_aggregate(const float* __restrict__ x,
                 const float* __restrict__ W,
                 const float* __restrict__ bias) {
    extern __shared__ float smem[];
    float* S   = smem + SM_S_OFF;
    float* Wsh = smem + SM_W_OFF;
    unsigned short* listAll = (unsigned short*)(smem + SM_LIST_OFF);

    const int tid  = threadIdx.x;
    const int warp = tid >> 5;
    const int lane = tid & 31;
    const int g    = blockIdx.x >> 3;            // 128 rows/block, 8 blocks/graph

    // ---- stage W (swizzled) ----
    for (int idx = tid; idx < 64 * 64; idx += THREADS) {
        int k = idx >> 6, d = idx & 63;
        Wsh[k * W_STRIDE + wphys(d & ~3) + (d & 3)] = W[idx];
    }

    // ---- Phase A: gather ----
    {
        const int h   = lane >> 4;
        const int l16 = lane & 15;
        const int off = l16 << 2;
        unsigned short* lst = listAll + warp * LISTCAP;
        const float* xg = x + ((size_t)g << 16);

        const int rowBase = blockIdx.x * ROWS_PER_BLOCK + warp * 16;
        unsigned wordNext = g_adj[rowBase * ROW_WORDS + lane];

        for (int i = 0; i < 16; i++) {
            const int lr = warp * 16 + i;
            unsigned word = wordNext;
            if (i < 15)
                wordNext = g_adj[(rowBase + i + 1) * ROW_WORDS + lane];
            g_adj[(rowBase + i) * ROW_WORDS + lane] = 0u;  // restore zeros

            // decode bitmap row -> compact neighbor list
            int cnt = __popc(word);
            int pre = cnt;
#pragma unroll
            for (int o = 1; o < 32; o <<= 1) {
                int v = __shfl_up_sync(FULLMASK, pre, o);
                if (lane >= o) pre += v;
            }
            int deg = __shfl_sync(FULLMASK, pre, 31);
            pre -= cnt;
            while (word) {
                int b = __ffs(word) - 1;
                word &= word - 1;
                if (pre < LISTCAP) lst[pre] = (unsigned short)((lane << 5) | b);
                pre++;
            }
            if (deg > LISTCAP) deg = LISTCAP;
            __syncwarp();

            // half-warp pair gather, unrolled x4, two f32x2 accumulator chains
            unsigned long long a0 = 0ull, a1 = 0ull, b0 = 0ull, b1 = 0ull;
            const int nfull = deg >> 1;
            int t = 0;
            for (; t + 4 <= nfull; t += 4) {
                int i0 = (int)lst[2 * t + h];
                int i1 = (int)lst[2 * (t + 1) + h];
                int i2 = (int)lst[2 * (t + 2) + h];
                int i3 = (int)lst[2 * (t + 3) + h];
                F4U v0, v1, v2, v3;
                v0.f = __ldg((const float4*)(xg + (i0 << 6) + off));
                v1.f = __ldg((const float4*)(xg + (i1 << 6) + off));
                v2.f = __ldg((const float4*)(xg + (i2 << 6) + off));
                v3.f = __ldg((const float4*)(xg + (i3 << 6) + off));
                a0 = add2(a0, v0.u[0]); a1 = add2(a1, v0.u[1]);
                b0 = add2(b0, v1.u[0]); b1 = add2(b1, v1.u[1]);
                a0 = add2(a0, v2.u[0]); a1 = add2(a1, v2.u[1]);
                b0 = add2(b0, v3.u[0]); b1 = add2(b1, v3.u[1]);
            }
            for (; t < nfull; t++) {
                int ni = (int)lst[2 * t + h];
                F4U v;
                v.f = __ldg((const float4*)(xg + (ni << 6) + off));
                a0 = add2(a0, v.u[0]);
                a1 = add2(a1, v.u[1]);
            }
            if ((deg & 1) && h == 0) {
                int ni = (int)lst[deg - 1];
                F4U v;
                v.f = __ldg((const float4*)(xg + (ni << 6) + off));
                b0 = add2(b0, v.u[0]);
                b1 = add2(b1, v.u[1]);
            }
            a0 = add2(a0, b0);
            a1 = add2(a1, b1);

            float s0 = lo2(a0), s1 = hi2(a0), s2 = lo2(a1), s3 = hi2(a1);
            s0 += __shfl_xor_sync(FULLMASK, s0, 16);
            s1 += __shfl_xor_sync(FULLMASK, s1, 16);
            s2 += __shfl_xor_sync(FULLMASK, s2, 16);
            s3 += __shfl_xor_sync(FULLMASK, s3, 16);
            if (h == 0) {
                float* Srow = &S[lr * S_STRIDE + 4 * l16];
                Srow[0] = s0; Srow[1] = s1; Srow[2] = s2; Srow[3] = s3;
            }
            __syncwarp();
        }
    }
    __syncthreads();

    // ---- Phase B: Y = S@W + bias, 4 rows x 8 dims / thread, f32x2 ----
    const int d0    = (lane & 7) * 8;
    const int rsub  = lane >> 3;
    const int rbase = warp * 16 + rsub * 4;
    const int pc0   = wphys(d0);
    const int pc1   = wphys(d0 + 4);

    unsigned long long acc[4][4];
    {
        unsigned long long bp[4];
#pragma unroll
        for (int p = 0; p < 4; p++)
            bp[p] = pack2(__ldg(&bias[d0 + 2 * p]), __ldg(&bias[d0 + 2 * p + 1]));
#pragma unroll
        for (int i = 0; i < 4; i++)
#pragma unroll
            for (int p = 0; p < 4; p++) acc[i][p] = bp[p];
    }

#pragma unroll 8
    for (int k = 0; k < 64; k++) {
        F4U wa, wb;
        wa.f = *reinterpret_cast<const float4*>(&Wsh[k * W_STRIDE + pc0]);
        wb.f = *reinterpret_cast<const float4*>(&Wsh[k * W_STRIDE + pc1]);
#pragma unroll
        for (int i = 0; i < 4; i++) {
            float s = S[(rbase + i) * S_STRIDE + k];
            unsigned long long sp = pack2(s, s);
            acc[i][0] = fma2(sp, wa.u[0], acc[i][0]);
            acc[i][1] = fma2(sp, wa.u[1], acc[i][1]);
            acc[i][2] = fma2(sp, wb.u[0], acc[i][2]);
            acc[i][3] = fma2(sp, wb.u[1], acc[i][3]);
        }
    }

    // ---- max-pool epilogue ----
    float m[8];
#pragma unroll
    for (int p = 0; p < 4; p++) {
        float m0 = lo2(acc[0][p]), m1 = hi2(acc[0][p]);
#pragma unroll
        for (int i = 1; i < 4; i++) {
            m0 = fmaxf(m0, lo2(acc[i][p]));
            m1 = fmaxf(m1, hi2(acc[i][p]));
        }
        m[2 * p] = m0;
        m[2 * p + 1] = m1;
    }
#pragma unroll
    for (int j = 0; j < 8; j++) {
        m[j] = fmaxf(m[j], __shfl_xor_sync(FULLMASK, m[j], 8));
        m[j] = fmaxf(m[j], __shfl_xor_sync(FULLMASK, m[j], 16));
    }
    if (rsub == 0) {
#pragma unroll
        for (int j = 0; j < 8; j++)
            atomicMax(&g_pooled[g * 64 + d0 + j], fmap(m[j]));
    }
}

// ---------------------------------------------------------------------------
// 3) MLP head: one block per graph, 256 threads, coalesced weight loads,
//    4-way k-split + smem reduce per layer.
// ---------------------------------------------------------------------------
__global__ __launch_bounds__(256)
void k_mlp(const float* __restrict__ w1, const float* __restrict__ b1,
           const float* __restrict__ w2, const float* __restrict__ b2,
           const float* __restrict__ w3, const float* __restrict__ b3,
           float* __restrict__ out) {
    __shared__ float h[64];
    __shared__ float red[4][64];
    __shared__ float outred[2];

    const int tid = threadIdx.x;
    const int d   = tid & 63;
    const int q   = tid >> 6;          // 0..3, k-chunk
    const int gr  = blockIdx.x;

    if (tid < 64) h[tid] = funmap(g_pooled[gr * 64 + tid]);
    __syncthreads();

    // layer 1
    {
        float p = 0.f;
        const int k0 = q * 16;
#pragma unroll
        for (int k = 0; k < 16; k++)
            p = fmaf(h[k0 + k], __ldg(&w1[(k0 + k) * 64 + d]), p);
        red[q][d] = p;
        __syncthreads();
        if (tid < 64) {
            float a = red[0][d] + red[1][d] + red[2][d] + red[3][d] + __ldg(&b1[d]);
            h[d] = tanhf(a);
        }
        __syncthreads();
    }
    // layer 2
    {
        float p = 0.f;
        const int k0 = q * 16;
#pragma unroll
        for (int k = 0; k < 16; k++)
            p = fmaf(h[k0 + k], __ldg(&w2[(k0 + k) * 64 + d]), p);
        red[q][d] = p;
        __syncthreads();
        if (tid < 64) {
            float a = red[0][d] + red[1][d] + red[2][d] + red[3][d] + __ldg(&b2[d]);
            h[d] = tanhf(a);
        }
        __syncthreads();
    }
    // layer 3: out[gr] = dot(h, w3) + b3  (2 warps, warp-reduce)
    if (tid < 64) {
        float p = h[tid] * __ldg(&w3[tid]);
#pragma unroll
        for (int o = 16; o; o >>= 1) p += __shfl_xor_sync(FULLMASK, p, o);
        if ((tid & 31) == 0) outred[tid >> 5] = p;
    }
    __syncthreads();
    if (tid == 0) out[gr] = outred[0] + outred[1] + __ldg(&b3[0]);
}

// ---------------------------------------------------------------------------
extern "C" void kernel_launch(void* const* d_in, const int* in_sizes, int n_in,
                              void* d_out, int out_size) {
    const float* x      = (const float*)d_in[0];
    const void*  eidx   = d_in[1];
    const float* weight = (const float*)d_in[4];
    const float* bias   = (const float*)d_in[5];
    const float* w1     = (const float*)d_in[6];
    const float* b1     = (const float*)d_in[7];
    const float* w2     = (const float*)d_in[8];
    const float* b2     = (const float*)d_in[9];
    const float* w3     = (const float*)d_in[10];
    const float* b3     = (const float*)d_in[11];
    float* out = (float*)d_out;

    cudaFuncSetAttribute(k_aggregate, cudaFuncAttributeMaxDynamicSharedMemorySize, SM_BYTES);

    k_detect<<<1, 32>>>(eidx);

    k_scatter<<<(EDGES / 2) / 256, 256>>>(eidx);

    k_aggregate<<<NNODES / ROWS_PER_BLOCK, THREADS, SM_BYTES>>>(x, weight, bias);

    k_mlp<<<B_, 256>>>(w1, b1, w2, b2, w3, b3, out);
}